// round 6
// baseline (speedup 1.0000x reference)
#include <cuda_runtime.h>
#include <cuda_bf16.h>
#include <cstdint>

// ===========================================================================
// CR8_reg_cond_mul_5 — mma.sync + ldmatrix (bf16 split precision), 512 thr.
//  class path:  x --W1--> h --cl2--> x2 --cl3--> logits[129]   (3-pass split)
//  reg path:    x --Wr--> r                                    (hi-only)
//  argmax in registers; ambiguous (gap<1e-3) recomputed in fp32.
//  tail: gathered [r;h] @ w2[super] (256x32) GEMV, 4 threads/position.
// ===========================================================================

#define NPOS  (16 * 8192)
#define RS    136          // bf16 plane row stride in elements
#define RSB   272          // bytes (17 * 16B -> conflict-free ldmatrix)

// ---------------- device-global prepped data -------------------------------
__device__ float g_W1[128 * 128];              // BN-folded fp32 W1 (fallback)
__device__ float g_b1[128];
__device__ float g_br[128];
// bf16 hi/lo weight images, row-major [o][k], stride 128.
// offsets (elements): L0=0, L1=16384, L2=32768, L3=49152 (136 rows)
__device__ __nv_bfloat16 g_whi[66560];
__device__ __nv_bfloat16 g_wlo[66560];

__device__ __forceinline__ float lrelu(float v) { return v >= 0.0f ? v : 0.01f * v; }

__device__ __forceinline__ uint32_t pack2(float a, float b) {
    __nv_bfloat162 t(__float2bfloat16(a), __float2bfloat16(b));
    return *reinterpret_cast<uint32_t*>(&t);
}
__device__ __forceinline__ uint32_t pack2_res(float a, float b, float* ra, float* rb) {
    __nv_bfloat16 ha = __float2bfloat16(a), hb = __float2bfloat16(b);
    *ra = a - __bfloat162float(ha);
    *rb = b - __bfloat162float(hb);
    __nv_bfloat162 t(ha, hb);
    return *reinterpret_cast<uint32_t*>(&t);
}
__device__ __forceinline__ void unpack2(uint32_t u, float* a, float* b) {
    __nv_bfloat162 t = *reinterpret_cast<__nv_bfloat162*>(&u);
    *a = __bfloat162float(t.x);
    *b = __bfloat162float(t.y);
}

__device__ __forceinline__ uint32_t smem_u32(const void* p) {
    uint32_t a;
    asm("{ .reg .u64 t; cvta.to.shared.u64 t, %1; cvt.u32.u64 %0, t; }"
        : "=r"(a) : "l"(p));
    return a;
}

__device__ __forceinline__ void mma16816(float* d,
    uint32_t a0, uint32_t a1, uint32_t a2, uint32_t a3,
    uint32_t b0, uint32_t b1)
{
    asm volatile(
        "mma.sync.aligned.m16n8k16.row.col.f32.bf16.bf16.f32 "
        "{%0,%1,%2,%3}, {%4,%5,%6,%7}, {%8,%9}, {%0,%1,%2,%3};"
        : "+f"(d[0]), "+f"(d[1]), "+f"(d[2]), "+f"(d[3])
        : "r"(a0), "r"(a1), "r"(a2), "r"(a3), "r"(b0), "r"(b1));
}

__device__ __forceinline__ void ldsm4(uint32_t* r, uint32_t addr) {
    asm volatile("ldmatrix.sync.aligned.m8n8.x4.shared.b16 {%0,%1,%2,%3}, [%4];"
        : "=r"(r[0]), "=r"(r[1]), "=r"(r[2]), "=r"(r[3]) : "r"(addr));
}

// ---------------- smem layout (byte offsets) -------------------------------
#define OFF_XHI    0               // 128*272 = 34816 each plane
#define OFF_XLO    34816
#define OFF_HHI    69632
#define OFF_HLO    104448
#define OFF_RHI    139264
#define OFF_WBUF   174080          // 144 rows * 272 = 39168 (padded for ldsm)
#define OFF_B1     213248
#define OFF_BR     213760
#define OFF_BC2    214272
#define OFF_BC3    214784          // 136 floats (576B slot)
#define OFF_MASK   215360
#define OFF_INDS   215872
#define OFF_PERM   216384
#define OFF_CNT    216896
#define OFF_NFLAG  216960
#define OFF_FLAGW  216976
#define OFF_XCOL   217488
#define OFF_HCOL   218000
#define OFF_X2COL  218512
#define OFF_LGCOL  219024
#define OFF_AB0    219536
#define OFF_AS0    220048
#define OFF_AI0    220560
#define OFF_AB1    221072
#define OFF_AS1    221584
#define OFF_AI1    222096
#define SMEM_REQ   222720

// ---------------------------------------------------------------------------
// prep kernel: BN fold + bf16 hi/lo split (row-major images)
// ---------------------------------------------------------------------------
__global__ void prep_kernel(
    const float* __restrict__ cl1_w, const float* __restrict__ cl1_b,
    const float* __restrict__ g1, const float* __restrict__ bt1,
    const float* __restrict__ m1, const float* __restrict__ v1,
    const float* __restrict__ cl2_w,
    const float* __restrict__ cl3_w,
    const float* __restrict__ reg_w, const float* __restrict__ reg_b,
    const float* __restrict__ gr, const float* __restrict__ btr,
    const float* __restrict__ mr, const float* __restrict__ vr)
{
    int idx = blockIdx.x * blockDim.x + threadIdx.x;
    if (idx < 128) {
        float s1 = g1[idx] * rsqrtf(v1[idx] + 1e-5f);
        float sr = gr[idx] * rsqrtf(vr[idx] + 1e-5f);
        g_b1[idx] = (cl1_b[idx] - m1[idx]) * s1 + bt1[idx];
        g_br[idx] = (reg_b[idx] - mr[idx]) * sr + btr[idx];
    }
    if (idx >= 4 * 136 * 128) return;
    int L = idx / (136 * 128);
    int rem = idx % (136 * 128);
    int row = rem / 128, k = rem % 128;
    if (L != 3 && row >= 128) return;

    float v;
    if (L == 0) {
        float s = g1[row] * rsqrtf(v1[row] + 1e-5f);
        v = cl1_w[row * 128 + k] * s;
        g_W1[row * 128 + k] = v;
    } else if (L == 1) {
        float s = gr[row] * rsqrtf(vr[row] + 1e-5f);
        v = reg_w[row * 128 + k] * s;
    } else if (L == 2) {
        v = cl2_w[row * 128 + k];
    } else {
        v = (row < 129) ? cl3_w[row * 128 + k] : 0.0f;
    }
    __nv_bfloat16 hi = __float2bfloat16(v);
    __nv_bfloat16 lo = __float2bfloat16(v - __bfloat162float(hi));
    static const int loff[4] = {0, 16384, 32768, 49152};
    int dst = loff[L] + row * 128 + k;
    g_whi[dst] = hi;
    g_wlo[dst] = lo;
}

// ---------------------------------------------------------------------------
__device__ __forceinline__ void copyW(const __nv_bfloat16* __restrict__ src,
                                      char* dst, int rows, int tid) {
    int total = rows * 16;
    const char* s = (const char*)src;
    for (int i = tid; i < total; i += 512) {
        int row = i >> 4, part = i & 15;
        *(uint4*)(dst + row * RSB + part * 16) =
            *(const uint4*)(s + row * 256 + part * 16);
    }
}

// Layer: acc[nt][4] += passes of W x X.  Pass order: WhXh, WhXl, WlXh.
// Warp computes 16 positions (wpos) x nt*8 outputs (obase).
template <int NTMAX>
__device__ __forceinline__ void run_layer(
    float (&acc)[NTMAX][4], int nt,
    uint32_t xhi_u, uint32_t xlo_u,
    const __nv_bfloat16* gwhi, const __nv_bfloat16* gwlo,
    char* wbuf, uint32_t wbuf_u, int wrows, int npasses,
    int tid, int wpos, int obase)
{
#pragma unroll
    for (int q = 0; q < NTMAX; ++q)
#pragma unroll
        for (int j = 0; j < 4; ++j) acc[q][j] = 0.0f;

    const int lane = tid & 31;
    const uint32_t a_off =
        (uint32_t)(wpos * 16 + (lane & 15)) * RSB + ((lane & 16) ? 16u : 0u);
    const uint32_t b_base =
        wbuf_u + (uint32_t)(obase + (lane & 7) + ((lane & 16) ? 8 : 0)) * RSB +
        ((lane & 8) ? 16u : 0u);

    for (int pass = 0; pass < npasses; ++pass) {
        if (pass == 0) {
            __syncthreads();                 // prior wbuf readers done
            copyW(gwhi, wbuf, wrows, tid);
            __syncthreads();
        } else if (pass == 2) {
            __syncthreads();
            copyW(gwlo, wbuf, wrows, tid);
            __syncthreads();
        }
        const uint32_t abase = ((pass == 1) ? xlo_u : xhi_u) + a_off;
#pragma unroll
        for (int kc = 0; kc < 8; ++kc) {
            uint32_t a[4];
            ldsm4(a, abase + kc * 32);
#pragma unroll
            for (int j = 0; j < (NTMAX + 1) / 2; ++j) {
                if (2 * j >= nt) break;
                uint32_t bfr[4];
                ldsm4(bfr, b_base + (uint32_t)(j * 16) * RSB + kc * 32);
                mma16816(acc[2 * j], a[0], a[1], a[2], a[3], bfr[0], bfr[1]);
                if (2 * j + 1 < nt)
                    mma16816(acc[2 * j + 1], a[0], a[1], a[2], a[3], bfr[2], bfr[3]);
            }
        }
    }
}

// epilogue: bias + lrelu, store bf16 hi (and optional lo residual) planes
__device__ __forceinline__ void epi_store8(
    float (&acc)[8][4], const float* bias,
    char* dsthi, char* dstlo, int tid, int wpos, int obase)
{
    const int lane = tid & 31;
    const int r = lane >> 2, cb = (lane & 3) * 2;
    const int p1 = wpos * 16 + r, p2 = p1 + 8;
#pragma unroll
    for (int q = 0; q < 8; ++q) {
        int o = obase + q * 8 + cb;
        float b0 = bias[o], b1 = bias[o + 1];
        float v0 = lrelu(acc[q][0] + b0), v1 = lrelu(acc[q][1] + b1);
        float v2 = lrelu(acc[q][2] + b0), v3 = lrelu(acc[q][3] + b1);
        if (dstlo) {
            float r0, r1, r2, r3;
            *(uint32_t*)(dsthi + p1 * RSB + o * 2) = pack2_res(v0, v1, &r0, &r1);
            *(uint32_t*)(dsthi + p2 * RSB + o * 2) = pack2_res(v2, v3, &r2, &r3);
            *(uint32_t*)(dstlo + p1 * RSB + o * 2) = pack2(r0, r1);
            *(uint32_t*)(dstlo + p2 * RSB + o * 2) = pack2(r2, r3);
        } else {
            *(uint32_t*)(dsthi + p1 * RSB + o * 2) = pack2(v0, v1);
            *(uint32_t*)(dsthi + p2 * RSB + o * 2) = pack2(v2, v3);
        }
    }
}

// ---------------------------------------------------------------------------
__global__ void __launch_bounds__(512, 1)
main_kernel(const float* __restrict__ x_in,
            const float* __restrict__ cl2_w, const float* __restrict__ cl2_b,
            const float* __restrict__ cl3_w, const float* __restrict__ cl3_b,
            const float* __restrict__ w2,    const float* __restrict__ b2,
            const float* __restrict__ w3,    const float* __restrict__ b3,
            float* __restrict__ out)
{
    extern __shared__ char sm[];
    char* Xhi = sm + OFF_XHI;
    char* Xlo = sm + OFF_XLO;
    char* Hhi = sm + OFF_HHI;
    char* Hlo = sm + OFF_HLO;
    char* Rhi = sm + OFF_RHI;
    char* Wbuf = sm + OFF_WBUF;
    float* b1s   = (float*)(sm + OFF_B1);
    float* brs   = (float*)(sm + OFF_BR);
    float* bc2   = (float*)(sm + OFF_BC2);
    float* bc3   = (float*)(sm + OFF_BC3);
    float* maskv = (float*)(sm + OFF_MASK);
    int*   inds  = (int*)(sm + OFF_INDS);
    int*   perm  = (int*)(sm + OFF_PERM);
    int*   cnt   = (int*)(sm + OFF_CNT);
    int*   nflag = (int*)(sm + OFF_NFLAG);
    int*   flagw = (int*)(sm + OFF_FLAGW);
    float* xcol  = (float*)(sm + OFF_XCOL);
    float* hcol  = (float*)(sm + OFF_HCOL);
    float* x2col = (float*)(sm + OFF_X2COL);
    float* lgcol = (float*)(sm + OFF_LGCOL);
    float* ab0   = (float*)(sm + OFF_AB0);
    float* as0   = (float*)(sm + OFF_AS0);
    int*   ai0   = (int*)(sm + OFF_AI0);
    float* ab1   = (float*)(sm + OFF_AB1);
    float* as1   = (float*)(sm + OFF_AS1);
    int*   ai1   = (int*)(sm + OFF_AI1);

    const uint32_t smu   = smem_u32(sm);
    const uint32_t xhi_u = smu + OFF_XHI;
    const uint32_t xlo_u = smu + OFF_XLO;
    const uint32_t hhi_u = smu + OFF_HHI;
    const uint32_t hlo_u = smu + OFF_HLO;
    const uint32_t wbuf_u = smu + OFF_WBUF;

    const int tid  = threadIdx.x;
    const int wid  = tid >> 5;
    const int wpos = wid >> 1;          // 0..7 : 16-position group
    const int wout = wid & 1;           // 0/1  : output half
    const int obase = wout * 64;
    const int tile = blockIdx.x;
    const int b    = tile >> 6;
    const int w0   = (tile & 63) * 128;
    const float* xb = x_in + (size_t)b * 128 * 8192 + w0;

    // ---- stage X transposed (Xt[p][k]) as bf16 hi/lo; biases; init -------
    {
        int w = tid & 127;
        for (int c = tid >> 7; c < 128; c += 4) {
            float v = xb[c * 8192 + w];
            __nv_bfloat16 hi = __float2bfloat16(v);
            float res = v - __bfloat162float(hi);
            *(__nv_bfloat16*)(Xhi + w * RSB + c * 2) = hi;
            *(__nv_bfloat16*)(Xlo + w * RSB + c * 2) = __float2bfloat16(res);
        }
    }
    if (tid < 128) {
        b1s[tid] = g_b1[tid];
        brs[tid] = g_br[tid];
        bc2[tid] = cl2_b[tid];
    }
    if (tid < 136) bc3[tid] = (tid < 129) ? cl3_b[tid] : 0.0f;
    if (tid == 0) *nflag = 0;
    if (tid < 16) cnt[tid] = 0;
    // run_layer's leading __syncthreads() orders the staging.

    const __nv_bfloat16* W0h = g_whi;            const __nv_bfloat16* W0l = g_wlo;
    const __nv_bfloat16* W1h = g_whi + 16384;
    const __nv_bfloat16* W2h = g_whi + 32768;    const __nv_bfloat16* W2l = g_wlo + 32768;
    const __nv_bfloat16* W3h = g_whi + 49152;    const __nv_bfloat16* W3l = g_wlo + 49152;

    {   // L0: h = lrelu(W1 x)   [3-pass]
        float acc[8][4];
        run_layer<8>(acc, 8, xhi_u, xlo_u, W0h, W0l, Wbuf, wbuf_u, 128, 3, tid, wpos, obase);
        epi_store8(acc, b1s, Hhi, Hlo, tid, wpos, obase);
    }
    {   // L1: r = lrelu(Wr x)   [hi-only]
        float acc[8][4];
        run_layer<8>(acc, 8, xhi_u, xlo_u, W1h, W1h, Wbuf, wbuf_u, 128, 1, tid, wpos, obase);
        epi_store8(acc, brs, Rhi, nullptr, tid, wpos, obase);
    }
    {   // L2: x2 = lrelu(cl2 h) [3-pass] -> overwrites X planes
        float acc[8][4];
        run_layer<8>(acc, 8, hhi_u, hlo_u, W2h, W2l, Wbuf, wbuf_u, 128, 3, tid, wpos, obase);
        epi_store8(acc, bc2, Xhi, Xlo, tid, wpos, obase);
    }
    {   // L3: logits = cl3 x2   [3-pass]; wout0: outs 0-63, wout1: 64-135
        float acc[9][4];
        int nt = wout ? 9 : 8;
        run_layer<9>(acc, nt, xhi_u, xlo_u, W3h, W3l, Wbuf, wbuf_u, 136, 3, tid, wpos, obase);

        const int lane = tid & 31;
        const int r = lane >> 2, cb = (lane & 3) * 2;
        const int p1 = wpos * 16 + r, p2 = p1 + 8;
        float bst1 = -3.4e38f, sec1 = -3.4e38f, bst2 = -3.4e38f, sec2 = -3.4e38f;
        int i1 = 0, i2 = 0;
        float m1v = 0.0f, m2v = 0.0f;
#pragma unroll
        for (int q = 0; q < 9; ++q) {
            if (q >= nt) break;
            int o0 = obase + q * 8 + cb, o1 = o0 + 1;
            float v0 = acc[q][0] + bc3[o0], v1 = acc[q][1] + bc3[o1];
            float v2 = acc[q][2] + bc3[o0], v3 = acc[q][3] + bc3[o1];
            if (o0 < 128) {
                if (v0 > bst1) { sec1 = bst1; bst1 = v0; i1 = o0; } else if (v0 > sec1) sec1 = v0;
                if (v2 > bst2) { sec2 = bst2; bst2 = v2; i2 = o0; } else if (v2 > sec2) sec2 = v2;
            } else if (o0 == 128) { m1v = v0; m2v = v2; }
            if (o1 < 128) {
                if (v1 > bst1) { sec1 = bst1; bst1 = v1; i1 = o1; } else if (v1 > sec1) sec1 = v1;
                if (v3 > bst2) { sec2 = bst2; bst2 = v3; i2 = o1; } else if (v3 > sec2) sec2 = v3;
            }
        }
#pragma unroll
        for (int off = 1; off < 4; off <<= 1) {
            float ob = __shfl_xor_sync(0xFFFFFFFFu, bst1, off);
            float os = __shfl_xor_sync(0xFFFFFFFFu, sec1, off);
            int   oi = __shfl_xor_sync(0xFFFFFFFFu, i1,  off);
            if (ob > bst1 || (ob == bst1 && oi < i1)) { sec1 = fmaxf(bst1, os); bst1 = ob; i1 = oi; }
            else sec1 = fmaxf(sec1, ob);
            ob = __shfl_xor_sync(0xFFFFFFFFu, bst2, off);
            os = __shfl_xor_sync(0xFFFFFFFFu, sec2, off);
            oi = __shfl_xor_sync(0xFFFFFFFFu, i2,  off);
            if (ob > bst2 || (ob == bst2 && oi < i2)) { sec2 = fmaxf(bst2, os); bst2 = ob; i2 = oi; }
            else sec2 = fmaxf(sec2, ob);
        }
        if ((lane & 3) == 0) {
            if (wout == 0) {
                ab0[p1] = bst1; as0[p1] = sec1; ai0[p1] = i1;
                ab0[p2] = bst2; as0[p2] = sec2; ai0[p2] = i2;
            } else {
                ab1[p1] = bst1; as1[p1] = sec1; ai1[p1] = i1;
                ab1[p2] = bst2; as1[p2] = sec2; ai1[p2] = i2;
                maskv[p1] = lrelu(m1v); maskv[p2] = lrelu(m2v);
            }
        }
    }
    __syncthreads();

    // ---- combine argmax halves; flag ambiguous ---------------------------
    if (tid < 128) {
        float b0v = ab0[tid], s0v = as0[tid];
        float b1v = ab1[tid], s1v = as1[tid];
        float best, sec; int idx;
        if (b1v > b0v) { best = b1v; idx = ai1[tid]; sec = fmaxf(b0v, s1v); }
        else           { best = b0v; idx = ai0[tid]; sec = fmaxf(s0v, b1v); }
        inds[tid] = idx;
        if (best - sec < 1e-3f) {
            int p = atomicAdd(nflag, 1);
            if (p < 128) flagw[p] = tid;
        }
    }
    __syncthreads();

    // ---- fp32 fallback for ambiguous argmax (rare) -----------------------
    int nf = *nflag; if (nf > 128) nf = 128;
    for (int i = 0; i < nf; ++i) {
        int w = flagw[i];
        if (tid < 128) xcol[tid] = xb[tid * 8192 + w];
        __syncthreads();
        if (tid < 256) {
            int o = tid >> 1, hh = tid & 1;
            const float* Wp = g_W1 + o * 128 + hh * 64;
            const float* xc = xcol + hh * 64;
            float s = 0.0f;
#pragma unroll 8
            for (int c = 0; c < 64; ++c) s = fmaf(Wp[c], xc[c], s);
            s += __shfl_xor_sync(0xFFFFFFFFu, s, 1);
            if (hh == 0) hcol[o] = lrelu(s + b1s[o]);
        }
        __syncthreads();
        if (tid < 256) {
            int o = tid >> 1, hh = tid & 1;
            const float* Wp = cl2_w + o * 128 + hh * 64;
            const float* xc = hcol + hh * 64;
            float s = 0.0f;
#pragma unroll 8
            for (int c = 0; c < 64; ++c) s = fmaf(Wp[c], xc[c], s);
            s += __shfl_xor_sync(0xFFFFFFFFu, s, 1);
            if (hh == 0) x2col[o] = lrelu(s + bc2[o]);
        }
        __syncthreads();
        if (tid < 256) {
            int o = tid >> 1, hh = tid & 1;
            const float* Wp = cl3_w + o * 128 + hh * 64;
            const float* xc = x2col + hh * 64;
            float s = 0.0f;
#pragma unroll 8
            for (int c = 0; c < 64; ++c) s = fmaf(Wp[c], xc[c], s);
            s += __shfl_xor_sync(0xFFFFFFFFu, s, 1);
            if (hh == 0) lgcol[o] = s + bc3[o];
        }
        __syncthreads();
        if (tid == 0) {
            float bv = lgcol[0]; int bi = 0;
            for (int o = 1; o < 128; ++o)
                if (lgcol[o] > bv) { bv = lgcol[o]; bi = o; }
            inds[w] = bi;
        }
        __syncthreads();
    }

    // ---- counting sort by super ------------------------------------------
    if (tid < 128) atomicAdd(&cnt[inds[tid] >> 4], 1);
    __syncthreads();
    if (tid == 0) {
        int run = 0;
#pragma unroll
        for (int s = 0; s < 8; ++s) { cnt[8 + s] = run; run += cnt[s]; }
    }
    __syncthreads();
    if (tid < 128) {
        int s = inds[tid] >> 4;
        int p = atomicAdd(&cnt[8 + s], 1);
        perm[p] = tid;
    }
    __syncthreads();

    // ---- gathered 256x32 GEMV + regression (4 threads / position) --------
    {
        const int pr = tid >> 2, t4 = tid & 3;
        const int w = perm[pr];
        const int ind = inds[w];
        const int s = ind >> 4;
        const char* plane = (t4 < 2) ? Rhi : Hhi;
        const char* pf = plane + w * RSB + ((t4 & 1) ? 128 : 0);
        const float* w2p = w2 + ((size_t)s * 256 + (size_t)t4 * 64) * 32;

        float acc[32];
#pragma unroll
        for (int o = 0; o < 32; ++o) acc[o] = 0.0f;

        for (int f2 = 0; f2 < 32; ++f2) {
            float v0, v1;
            unpack2(*(const uint32_t*)(pf + f2 * 4), &v0, &v1);
            const float4* wr0 = (const float4*)(w2p + (2 * f2) * 32);
            const float4* wr1 = (const float4*)(w2p + (2 * f2 + 1) * 32);
#pragma unroll
            for (int q = 0; q < 8; ++q) {
                float4 t0 = wr0[q];
                acc[q * 4 + 0] = fmaf(v0, t0.x, acc[q * 4 + 0]);
                acc[q * 4 + 1] = fmaf(v0, t0.y, acc[q * 4 + 1]);
                acc[q * 4 + 2] = fmaf(v0, t0.z, acc[q * 4 + 2]);
                acc[q * 4 + 3] = fmaf(v0, t0.w, acc[q * 4 + 3]);
            }
#pragma unroll
            for (int q = 0; q < 8; ++q) {
                float4 t1 = wr1[q];
                acc[q * 4 + 0] = fmaf(v1, t1.x, acc[q * 4 + 0]);
                acc[q * 4 + 1] = fmaf(v1, t1.y, acc[q * 4 + 1]);
                acc[q * 4 + 2] = fmaf(v1, t1.z, acc[q * 4 + 2]);
                acc[q * 4 + 3] = fmaf(v1, t1.w, acc[q * 4 + 3]);
            }
        }
#pragma unroll
        for (int o = 0; o < 32; ++o) {
            acc[o] += __shfl_xor_sync(0xFFFFFFFFu, acc[o], 1);
            acc[o] += __shfl_xor_sync(0xFFFFFFFFu, acc[o], 2);
        }

        if (t4 == 0) {
            float reg = b3[ind];
            const float* b2p = b2 + s * 32;
            const float* w3p = w3 + ind * 32;
#pragma unroll
            for (int o = 0; o < 32; ++o) {
                float y = lrelu(acc[o] + b2p[o]);
                reg = fmaf(y, w3p[o], reg);
            }
            int n = b * 8192 + w0 + w;
            out[n] = ((float)ind + reg) * (1.0f / 128.0f);
            out[NPOS + n] = maskv[w];
        }
    }
}

// ---------------------------------------------------------------------------
extern "C" void kernel_launch(void* const* d_in, const int* in_sizes, int n_in,
                              void* d_out, int out_size)
{
    (void)in_sizes; (void)n_in; (void)out_size;
    const float* x_in   = (const float*)d_in[0];
    const float* cl1_w  = (const float*)d_in[1];
    const float* cl1_b  = (const float*)d_in[2];
    const float* cl1_g  = (const float*)d_in[3];
    const float* cl1_bt = (const float*)d_in[4];
    const float* cl1_m  = (const float*)d_in[5];
    const float* cl1_v  = (const float*)d_in[6];
    const float* cl2_w  = (const float*)d_in[7];
    const float* cl2_b  = (const float*)d_in[8];
    const float* cl3_w  = (const float*)d_in[9];
    const float* cl3_b  = (const float*)d_in[10];
    const float* reg1_w = (const float*)d_in[11];
    const float* reg1_b = (const float*)d_in[12];
    const float* reg1_g = (const float*)d_in[13];
    const float* reg1_bt= (const float*)d_in[14];
    const float* reg1_m = (const float*)d_in[15];
    const float* reg1_v = (const float*)d_in[16];
    const float* w2     = (const float*)d_in[17];
    const float* b2     = (const float*)d_in[18];
    const float* w3     = (const float*)d_in[19];
    const float* b3     = (const float*)d_in[20];
    float* out = (float*)d_out;

    cudaFuncSetAttribute(main_kernel,
                         cudaFuncAttributeMaxDynamicSharedMemorySize, SMEM_REQ);

    prep_kernel<<<(4 * 136 * 128 + 255) / 256, 256>>>(
        cl1_w, cl1_b, cl1_g, cl1_bt, cl1_m, cl1_v,
        cl2_w, cl3_w,
        reg1_w, reg1_b, reg1_g, reg1_bt, reg1_m, reg1_v);

    main_kernel<<<1024, 512, SMEM_REQ>>>(x_in, cl2_w, cl2_b, cl3_w, cl3_b,
                                         w2, b2, w3, b3, out);
}

// round 9
// speedup vs baseline: 2.0886x; 2.0886x over previous
#include <cuda_runtime.h>

// ---------------------------------------------------------------------------
// CR8_reg_cond_mul_5: fused per-position MLP cascade (fp32, FFMA).
//   h  = lrelu(BN1(W1 x))          (BN folded into W1,b1 by prep kernel)
//   r  = lrelu(BNr(Wr x))
//   x2 = lrelu(W2c h + b2c)
//   lg = W3c x2 + b3c              (129 outputs: 128 logits + mask channel)
//   mask = lrelu(lg[128]); ind = argmax(lg[0:128]); s = ind>>4
//   y  = lrelu([r;h] @ w2[s] + b2[s])   (256x32)  <- super-grouped, smem w2
//   reg = y . w3[ind] + b3[ind]
//   x_real = (ind + reg)/128
// Output: [x_real (131072 f32) | mask (131072 f32)]
// ---------------------------------------------------------------------------

#define NPOS    (16 * 8192)
#define TILE    128
#define STRIDE  132            // 128 + 4 pad, keeps float4 alignment

__device__ float g_W1[128 * 128];
__device__ float g_b1[128];
__device__ float g_Wr[128 * 128];
__device__ float g_br[128];

__device__ __forceinline__ float lrelu(float v) {
    return v >= 0.0f ? v : 0.01f * v;
}

// Fold batch-norm into conv weights: W'[o][c] = W[o][c]*s[o],
// b'[o] = (b[o]-m[o])*s[o] + beta[o],  s[o] = g[o]/sqrt(v[o]+eps)
__global__ void prep_kernel(
    const float* __restrict__ cl1_w, const float* __restrict__ cl1_b,
    const float* __restrict__ g1, const float* __restrict__ bt1,
    const float* __restrict__ m1, const float* __restrict__ v1,
    const float* __restrict__ reg_w, const float* __restrict__ reg_b,
    const float* __restrict__ gr, const float* __restrict__ btr,
    const float* __restrict__ mr, const float* __restrict__ vr)
{
    int idx = blockIdx.x * blockDim.x + threadIdx.x;
    if (idx < 128 * 128) {
        int o = idx >> 7;
        float s1 = g1[o] * rsqrtf(v1[o] + 1e-5f);
        float sr = gr[o] * rsqrtf(vr[o] + 1e-5f);
        g_W1[idx] = cl1_w[idx] * s1;
        g_Wr[idx] = reg_w[idx] * sr;
        if (idx < 128) {
            int oo = idx;
            float ss1 = g1[oo] * rsqrtf(v1[oo] + 1e-5f);
            float ssr = gr[oo] * rsqrtf(vr[oo] + 1e-5f);
            g_b1[oo] = (cl1_b[oo] - m1[oo]) * ss1 + bt1[oo];
            g_br[oo] = (reg_b[oo] - mr[oo]) * ssr + btr[oo];
        }
    }
}

// 128x128x128 GEMM: Cs[o][p] = act(sum_k W[o][k]*Bs[k][p] + bias[o])
// W from global memory ([O][128] row-major), Bs/Cs in smem (STRIDE-pitched).
// Safe for Cs == Bs (barrier before epilogue writes).
__device__ __forceinline__ void gemm128(
    const float* __restrict__ W, const float* __restrict__ bias,
    const float* Bs, float* Cs, float* Wt, int tid, bool relu)
{
    const int ty = tid >> 4, tx = tid & 15;
    const int o0 = ty * 8, p0 = tx * 8;

    float acc[8][8];
#pragma unroll
    for (int i = 0; i < 8; ++i)
#pragma unroll
        for (int j = 0; j < 8; ++j) acc[i][j] = 0.0f;

    for (int kc = 0; kc < 8; ++kc) {
        __syncthreads();
        // stage W chunk transposed: Wt[k][o] = W[o][kc*16+k], k in [0,16)
        {
            int base = tid * 8;
            int k0 = base & 15;          // 0 or 8
            int o  = base >> 4;          // 0..127
            const float* src = &W[o * 128 + kc * 16 + k0];
            float4 v0 = *(const float4*)(src);
            float4 v1 = *(const float4*)(src + 4);
            Wt[(k0 + 0) * STRIDE + o] = v0.x;
            Wt[(k0 + 1) * STRIDE + o] = v0.y;
            Wt[(k0 + 2) * STRIDE + o] = v0.z;
            Wt[(k0 + 3) * STRIDE + o] = v0.w;
            Wt[(k0 + 4) * STRIDE + o] = v1.x;
            Wt[(k0 + 5) * STRIDE + o] = v1.y;
            Wt[(k0 + 6) * STRIDE + o] = v1.z;
            Wt[(k0 + 7) * STRIDE + o] = v1.w;
        }
        __syncthreads();
#pragma unroll
        for (int k = 0; k < 16; ++k) {
            float4 a0 = *(const float4*)&Wt[k * STRIDE + o0];
            float4 a1 = *(const float4*)&Wt[k * STRIDE + o0 + 4];
            const float* br = &Bs[(kc * 16 + k) * STRIDE + p0];
            float4 b0 = *(const float4*)(br);
            float4 b1 = *(const float4*)(br + 4);
            float a[8] = {a0.x, a0.y, a0.z, a0.w, a1.x, a1.y, a1.z, a1.w};
            float bb[8] = {b0.x, b0.y, b0.z, b0.w, b1.x, b1.y, b1.z, b1.w};
#pragma unroll
            for (int i = 0; i < 8; ++i)
#pragma unroll
                for (int j = 0; j < 8; ++j)
                    acc[i][j] = fmaf(a[i], bb[j], acc[i][j]);
        }
    }
    __syncthreads();   // all Bs reads done -> safe even when Cs aliases Bs
#pragma unroll
    for (int i = 0; i < 8; ++i) {
        float bi = bias[o0 + i];
#pragma unroll
        for (int j = 0; j < 8; ++j) {
            float v = acc[i][j] + bi;
            if (relu) v = lrelu(v);
            Cs[(o0 + i) * STRIDE + p0 + j] = v;
        }
    }
}

__global__ void __launch_bounds__(256, 1)
main_kernel(const float* __restrict__ x_in,
            const float* __restrict__ cl2_w, const float* __restrict__ cl2_b,
            const float* __restrict__ cl3_w, const float* __restrict__ cl3_b,
            const float* __restrict__ w2,    const float* __restrict__ b2,
            const float* __restrict__ w3,    const float* __restrict__ b3,
            float* __restrict__ out)
{
    extern __shared__ float smem[];
    float* Xs    = smem;                       // 128*STRIDE  (X, X2, logits, then w2 stage)
    float* Hs    = Xs + 128 * STRIDE;          // 128*STRIDE
    float* Rs    = Hs + 128 * STRIDE;          // 128*STRIDE
    float* Wt    = Rs + 128 * STRIDE;          // 16*STRIDE
    float* maskv = Wt + 16 * STRIDE;           // 128
    int*   inds  = (int*)(maskv + 128);        // 128
    int*   perm  = inds + 128;                 // 128
    int*   cnt   = perm + 128;                 // 16 (counts + running offsets)
    int*   starts= cnt + 16;                   // 8 (group start offsets)

    const int tid  = threadIdx.x;
    const int tile = blockIdx.x;               // 0..1023
    const int b    = tile >> 6;                // 64 tiles per batch image
    const int w0   = (tile & 63) * TILE;
    const float* xb = x_in + (size_t)b * 128 * 8192 + w0;

    // ---- load X tile: Xs[c][w] -------------------------------------------
#pragma unroll
    for (int i = 0; i < 64; ++i) {
        int idx = i * 256 + tid;
        int c = idx >> 7, w = idx & 127;
        Xs[c * STRIDE + w] = xb[c * 8192 + w];
    }

    // ---- dense cascade ----------------------------------------------------
    gemm128(g_W1, g_b1, Xs, Hs, Wt, tid, true);   // h
    gemm128(g_Wr, g_br, Xs, Rs, Wt, tid, true);   // r   (Xs dead after this)
    gemm128(cl2_w, cl2_b, Hs, Xs, Wt, tid, true); // x2 -> Xs
    __syncthreads();

    // ---- mask channel (row 128 of cl3) before logits clobber Xs ----------
    if (tid < 128) {
        int w = tid;
        float m = cl3_b[128];
        const float* wrow = cl3_w + 128 * 128;
#pragma unroll 8
        for (int c = 0; c < 128; ++c)
            m = fmaf(wrow[c], Xs[c * STRIDE + w], m);
        maskv[w] = lrelu(m);
    }

    gemm128(cl3_w, cl3_b, Xs, Xs, Wt, tid, false); // logits (in place)
    __syncthreads();

    // ---- argmax over 128 logits per position -----------------------------
    if (tid < 128) {
        int w = tid;
        float best = Xs[w];
        int bi = 0;
#pragma unroll 8
        for (int o = 1; o < 128; ++o) {
            float v = Xs[o * STRIDE + w];
            if (v > best) { best = v; bi = o; }
        }
        inds[w] = bi;
    }
    if (tid < 16) cnt[tid] = 0;
    __syncthreads();

    // ---- counting sort by super ------------------------------------------
    if (tid < 128) atomicAdd(&cnt[inds[tid] >> 4], 1);
    __syncthreads();
    if (tid == 0) {
        int run = 0;
#pragma unroll
        for (int s = 0; s < 8; ++s) { starts[s] = run; cnt[8 + s] = run; run += cnt[s]; }
    }
    __syncthreads();
    if (tid < 128) {
        int s = inds[tid] >> 4;
        int p = atomicAdd(&cnt[8 + s], 1);
        perm[p] = tid;
    }
    // (barrier at top of the group loop orders the scatter)

    // ---- super-grouped GEMV: stage w2[s] in smem once per group ----------
    // Xs region is dead (logits consumed) -> reuse as 32KB w2 staging buffer.
    // Barriers run unconditionally for all 8 groups: every thread executes an
    // identical barrier sequence (no data-dependent convergence questions).
    {
        const int warp = tid >> 5, lane = tid & 31;
        float* wsbuf = Xs;                 // 8192 floats
        for (int s = 0; s < 8; ++s) {
            const int c = cnt[s];
            __syncthreads();               // prior group's readers (and argmax/Xs) done
            if (c != 0) {
                const float4* src = (const float4*)(w2 + (size_t)s * 8192);
                float4* dst = (float4*)wsbuf;
                for (int i = tid; i < 2048; i += 256) dst[i] = src[i];
            }
            __syncthreads();
            if (c != 0) {
                const int start = starts[s];
                const int end   = start + c;
                const float b2v = b2[s * 32 + lane];
                for (int idx = start + warp; idx < end; idx += 8) {
                    const int w = perm[idx];
                    const int ind = inds[w];
                    const float* rcol = Rs + w;
                    const float* hcol = Hs + w;
                    float acc = 0.0f;
#pragma unroll 8
                    for (int f = 0; f < 128; ++f)
                        acc = fmaf(rcol[f * STRIDE], wsbuf[f * 32 + lane], acc);
#pragma unroll 8
                    for (int f = 0; f < 128; ++f)
                        acc = fmaf(hcol[f * STRIDE], wsbuf[(128 + f) * 32 + lane], acc);
                    float y = lrelu(acc + b2v);
                    float term = y * w3[ind * 32 + lane];
#pragma unroll
                    for (int off = 16; off > 0; off >>= 1)
                        term += __shfl_xor_sync(0xFFFFFFFFu, term, off);
                    if (lane == 0) {
                        int n = b * 8192 + w0 + w;
                        out[n] = ((float)ind + term + b3[ind]) * (1.0f / 128.0f);
                    }
                }
            }
        }
    }

    // ---- mask output ------------------------------------------------------
    if (tid < 128) {
        int n = b * 8192 + w0 + tid;
        out[NPOS + n] = maskv[tid];
    }
}

// ---------------------------------------------------------------------------

static const size_t SMEM_BYTES =
    (size_t)(3 * 128 * STRIDE + 16 * STRIDE + 128) * sizeof(float)
    + (size_t)(128 + 128 + 16 + 8) * sizeof(int);

extern "C" void kernel_launch(void* const* d_in, const int* in_sizes, int n_in,
                              void* d_out, int out_size)
{
    (void)in_sizes; (void)n_in; (void)out_size;
    const float* x_in   = (const float*)d_in[0];
    const float* cl1_w  = (const float*)d_in[1];
    const float* cl1_b  = (const float*)d_in[2];
    const float* cl1_g  = (const float*)d_in[3];
    const float* cl1_bt = (const float*)d_in[4];
    const float* cl1_m  = (const float*)d_in[5];
    const float* cl1_v  = (const float*)d_in[6];
    const float* cl2_w  = (const float*)d_in[7];
    const float* cl2_b  = (const float*)d_in[8];
    const float* cl3_w  = (const float*)d_in[9];
    const float* cl3_b  = (const float*)d_in[10];
    const float* reg1_w = (const float*)d_in[11];
    const float* reg1_b = (const float*)d_in[12];
    const float* reg1_g = (const float*)d_in[13];
    const float* reg1_bt= (const float*)d_in[14];
    const float* reg1_m = (const float*)d_in[15];
    const float* reg1_v = (const float*)d_in[16];
    const float* w2     = (const float*)d_in[17];
    const float* b2     = (const float*)d_in[18];
    const float* w3     = (const float*)d_in[19];
    const float* b3     = (const float*)d_in[20];
    float* out = (float*)d_out;

    cudaFuncSetAttribute(main_kernel,
                         cudaFuncAttributeMaxDynamicSharedMemorySize,
                         (int)SMEM_BYTES);

    prep_kernel<<<64, 256>>>(cl1_w, cl1_b, cl1_g, cl1_bt, cl1_m, cl1_v,
                             reg1_w, reg1_b, reg1_g, reg1_bt, reg1_m, reg1_v);
    main_kernel<<<1024, 256, SMEM_BYTES>>>(x_in, cl2_w, cl2_b, cl3_w, cl3_b,
                                           w2, b2, w3, b3, out);
}

// round 10
// speedup vs baseline: 2.1147x; 1.0125x over previous
#include <cuda_runtime.h>

// ---------------------------------------------------------------------------
// CR8_reg_cond_mul_5: fused per-position MLP cascade (fp32, FFMA2 GEMMs).
//   h  = lrelu(BN1(W1 x))          (BN folded into W1,b1 by prep kernel)
//   r  = lrelu(BNr(Wr x))
//   x2 = lrelu(W2c h + b2c)
//   lg = W3c x2 + b3c              (129 outputs: 128 logits + mask channel)
//   mask = lrelu(lg[128]); ind = argmax(lg[0:128]); s = ind>>4
//   y  = lrelu([r;h] @ w2[s] + b2[s])   (256x32, sorted gather tail)
//   reg = y . w3[ind] + b3[ind]
//   x_real = (ind + reg)/128
// GEMM inner loops use fma.rn.f32x2 (FFMA2): 2 fp32 FMAs per instruction,
// position-pairs packed in B, dup-packed weights in smem for A.
// Bit-identical numerics to the scalar-FFMA version.
// Output: [x_real (131072 f32) | mask (131072 f32)]
// ---------------------------------------------------------------------------

#define NPOS    (16 * 8192)
#define TILE    128
#define STRIDE  132            // 128 + 4 pad (floats), keeps 16B alignment

__device__ float g_W1[128 * 128];
__device__ float g_b1[128];
__device__ float g_Wr[128 * 128];
__device__ float g_br[128];

__device__ __forceinline__ float lrelu(float v) {
    return v >= 0.0f ? v : 0.01f * v;
}

__device__ __forceinline__ unsigned long long dup2(float f) {
    unsigned long long r;
    asm("mov.b64 %0, {%1, %1};" : "=l"(r) : "f"(f));
    return r;
}
__device__ __forceinline__ void unpk2(unsigned long long v, float* lo, float* hi) {
    asm("mov.b64 {%0, %1}, %2;" : "=f"(*lo), "=f"(*hi) : "l"(v));
}
__device__ __forceinline__ void ffma2(unsigned long long& d,
                                      unsigned long long a,
                                      unsigned long long b) {
    asm("fma.rn.f32x2 %0, %1, %2, %0;" : "+l"(d) : "l"(a), "l"(b));
}

// Fold batch-norm into conv weights.
__global__ void prep_kernel(
    const float* __restrict__ cl1_w, const float* __restrict__ cl1_b,
    const float* __restrict__ g1, const float* __restrict__ bt1,
    const float* __restrict__ m1, const float* __restrict__ v1,
    const float* __restrict__ reg_w, const float* __restrict__ reg_b,
    const float* __restrict__ gr, const float* __restrict__ btr,
    const float* __restrict__ mr, const float* __restrict__ vr)
{
    int idx = blockIdx.x * blockDim.x + threadIdx.x;
    if (idx < 128 * 128) {
        int o = idx >> 7;
        float s1 = g1[o] * rsqrtf(v1[o] + 1e-5f);
        float sr = gr[o] * rsqrtf(vr[o] + 1e-5f);
        g_W1[idx] = cl1_w[idx] * s1;
        g_Wr[idx] = reg_w[idx] * sr;
        if (idx < 128) {
            int oo = idx;
            float ss1 = g1[oo] * rsqrtf(v1[oo] + 1e-5f);
            float ssr = gr[oo] * rsqrtf(vr[oo] + 1e-5f);
            g_b1[oo] = (cl1_b[oo] - m1[oo]) * ss1 + bt1[oo];
            g_br[oo] = (reg_b[oo] - mr[oo]) * ssr + btr[oo];
        }
    }
}

// 128x128x128 GEMM with FFMA2. Cs[o][p] = act(sum_k W[o][k]*Bs[k][p] + b[o]).
// W from gmem ([O][128] row-major), Bs/Cs smem (STRIDE-pitched fp32).
// Wt2: smem staging of a 16-k chunk, dup-packed: Wt2[k*128+o] = {w,w}.
// Safe for Cs == Bs (barrier before epilogue writes).
__device__ __forceinline__ void gemm128(
    const float* __restrict__ W, const float* __restrict__ bias,
    const float* Bs, float* Cs, unsigned long long* Wt2, int tid, bool relu)
{
    const int ty = tid >> 4, tx = tid & 15;
    const int o0 = ty * 8, p0 = tx * 8;

    unsigned long long acc[8][4];
#pragma unroll
    for (int i = 0; i < 8; ++i)
#pragma unroll
        for (int j = 0; j < 4; ++j) acc[i][j] = 0ULL;   // {0.0f, 0.0f}

    for (int kc = 0; kc < 8; ++kc) {
        __syncthreads();
        // stage dup-packed W chunk: Wt2[k*128+o] = {W[o][kc*16+k]} x2
        {
            int base = tid * 8;
            int k0 = base & 15;          // 0 or 8
            int o  = base >> 4;          // 0..127
            const float* src = &W[o * 128 + kc * 16 + k0];
            float4 v0 = *(const float4*)(src);
            float4 v1 = *(const float4*)(src + 4);
            Wt2[(k0 + 0) * 128 + o] = dup2(v0.x);
            Wt2[(k0 + 1) * 128 + o] = dup2(v0.y);
            Wt2[(k0 + 2) * 128 + o] = dup2(v0.z);
            Wt2[(k0 + 3) * 128 + o] = dup2(v0.w);
            Wt2[(k0 + 4) * 128 + o] = dup2(v1.x);
            Wt2[(k0 + 5) * 128 + o] = dup2(v1.y);
            Wt2[(k0 + 6) * 128 + o] = dup2(v1.z);
            Wt2[(k0 + 7) * 128 + o] = dup2(v1.w);
        }
        __syncthreads();
#pragma unroll
        for (int k = 0; k < 16; ++k) {
            const ulonglong2* arow = (const ulonglong2*)&Wt2[k * 128 + o0];
            ulonglong2 a01 = arow[0];
            ulonglong2 a23 = arow[1];
            ulonglong2 a45 = arow[2];
            ulonglong2 a67 = arow[3];
            const ulonglong2* brow =
                (const ulonglong2*)&Bs[(kc * 16 + k) * STRIDE + p0];
            ulonglong2 b01 = brow[0];
            ulonglong2 b23 = brow[1];
            unsigned long long a[8] = {a01.x, a01.y, a23.x, a23.y,
                                       a45.x, a45.y, a67.x, a67.y};
            unsigned long long bb[4] = {b01.x, b01.y, b23.x, b23.y};
#pragma unroll
            for (int i = 0; i < 8; ++i)
#pragma unroll
                for (int j = 0; j < 4; ++j)
                    ffma2(acc[i][j], a[i], bb[j]);
        }
    }
    __syncthreads();   // all Bs reads done -> safe even when Cs aliases Bs
#pragma unroll
    for (int i = 0; i < 8; ++i) {
        float bi = bias[o0 + i];
        float* crow = &Cs[(o0 + i) * STRIDE + p0];
#pragma unroll
        for (int j = 0; j < 4; ++j) {
            float lo, hi;
            unpk2(acc[i][j], &lo, &hi);
            float v0 = lo + bi, v1 = hi + bi;
            if (relu) { v0 = lrelu(v0); v1 = lrelu(v1); }
            float2 st = {v0, v1};
            *(float2*)(crow + 2 * j) = st;
        }
    }
}

__global__ void __launch_bounds__(256, 1)
main_kernel(const float* __restrict__ x_in,
            const float* __restrict__ cl2_w, const float* __restrict__ cl2_b,
            const float* __restrict__ cl3_w, const float* __restrict__ cl3_b,
            const float* __restrict__ w2,    const float* __restrict__ b2,
            const float* __restrict__ w3,    const float* __restrict__ b3,
            float* __restrict__ out)
{
    extern __shared__ float smem[];
    float* Xs    = smem;                       // 128*STRIDE (X, X2, logits)
    float* Hs    = Xs + 128 * STRIDE;          // 128*STRIDE
    float* Rs    = Hs + 128 * STRIDE;          // 128*STRIDE
    unsigned long long* Wt2 = (unsigned long long*)(Rs + 128 * STRIDE); // 16*128 u64
    float* maskv = (float*)(Wt2 + 16 * 128);   // 128
    int*   inds  = (int*)(maskv + 128);        // 128
    int*   perm  = inds + 128;                 // 128
    int*   cnt   = perm + 128;                 // 16

    const int tid  = threadIdx.x;
    const int tile = blockIdx.x;               // 0..1023
    const int b    = tile >> 6;
    const int w0   = (tile & 63) * TILE;
    const float* xb = x_in + (size_t)b * 128 * 8192 + w0;

    // ---- load X tile: Xs[c][w] -------------------------------------------
#pragma unroll
    for (int i = 0; i < 64; ++i) {
        int idx = i * 256 + tid;
        int c = idx >> 7, w = idx & 127;
        Xs[c * STRIDE + w] = xb[c * 8192 + w];
    }

    // ---- dense cascade (FFMA2 GEMMs) -------------------------------------
    gemm128(g_W1, g_b1, Xs, Hs, Wt2, tid, true);   // h
    gemm128(g_Wr, g_br, Xs, Rs, Wt2, tid, true);   // r  (Xs dead after this)
    gemm128(cl2_w, cl2_b, Hs, Xs, Wt2, tid, true); // x2 -> Xs
    __syncthreads();

    // ---- mask channel (row 128 of cl3) before logits clobber Xs ----------
    if (tid < 128) {
        int w = tid;
        float m = cl3_b[128];
        const float* wrow = cl3_w + 128 * 128;
#pragma unroll 8
        for (int c = 0; c < 128; ++c)
            m = fmaf(wrow[c], Xs[c * STRIDE + w], m);
        maskv[w] = lrelu(m);
    }

    gemm128(cl3_w, cl3_b, Xs, Xs, Wt2, tid, false); // logits (in place)
    __syncthreads();

    // ---- argmax over 128 logits per position -----------------------------
    if (tid < 128) {
        int w = tid;
        float best = Xs[w];
        int bi = 0;
#pragma unroll 8
        for (int o = 1; o < 128; ++o) {
            float v = Xs[o * STRIDE + w];
            if (v > best) { best = v; bi = o; }
        }
        inds[w] = bi;
    }
    if (tid < 16) cnt[tid] = 0;
    __syncthreads();

    // ---- counting sort by super (w2 gather coherence) --------------------
    if (tid < 128) atomicAdd(&cnt[inds[tid] >> 4], 1);
    __syncthreads();
    if (tid == 0) {
        int run = 0;
#pragma unroll
        for (int s = 0; s < 8; ++s) { cnt[8 + s] = run; run += cnt[s]; }
    }
    __syncthreads();
    if (tid < 128) {
        int s = inds[tid] >> 4;
        int p = atomicAdd(&cnt[8 + s], 1);
        perm[p] = tid;
    }
    __syncthreads();

    // ---- gathered 256x32 GEMV + final regression (2 threads/pos) ---------
    {
        const int pr = tid >> 1, t2 = tid & 1;
        const int w = perm[pr];
        const int ind = inds[w];
        const int s = ind >> 4;
        const float* buf = t2 ? Hs : Rs;
        const float* w2p = w2 + ((size_t)s * 256 + (size_t)t2 * 128) * 32;

        float acc[32];
#pragma unroll
        for (int o = 0; o < 32; ++o) acc[o] = 0.0f;

#pragma unroll 2
        for (int f = 0; f < 128; ++f) {
            float v = buf[f * STRIDE + w];
            const float4* wr = (const float4*)(w2p + f * 32);
#pragma unroll
            for (int q = 0; q < 8; ++q) {
                float4 t = wr[q];
                acc[q * 4 + 0] = fmaf(v, t.x, acc[q * 4 + 0]);
                acc[q * 4 + 1] = fmaf(v, t.y, acc[q * 4 + 1]);
                acc[q * 4 + 2] = fmaf(v, t.z, acc[q * 4 + 2]);
                acc[q * 4 + 3] = fmaf(v, t.w, acc[q * 4 + 3]);
            }
        }
#pragma unroll
        for (int o = 0; o < 32; ++o)
            acc[o] += __shfl_xor_sync(0xFFFFFFFFu, acc[o], 1);

        float reg = b3[ind];
        const float* b2p = b2 + s * 32;
        const float* w3p = w3 + ind * 32;
#pragma unroll
        for (int o = 0; o < 32; ++o) {
            float y = lrelu(acc[o] + b2p[o]);
            reg = fmaf(y, w3p[o], reg);
        }
        if (t2 == 0) {
            int n = b * 8192 + w0 + w;
            out[n] = ((float)ind + reg) * (1.0f / 128.0f);
            out[NPOS + n] = maskv[w];
        }
    }
}

// ---------------------------------------------------------------------------

static const size_t SMEM_BYTES =
    (size_t)(3 * 128 * STRIDE) * sizeof(float)
    + (size_t)(16 * 128) * sizeof(unsigned long long)
    + (size_t)128 * sizeof(float)
    + (size_t)(128 + 128 + 16) * sizeof(int);

extern "C" void kernel_launch(void* const* d_in, const int* in_sizes, int n_in,
                              void* d_out, int out_size)
{
    (void)in_sizes; (void)n_in; (void)out_size;
    const float* x_in   = (const float*)d_in[0];
    const float* cl1_w  = (const float*)d_in[1];
    const float* cl1_b  = (const float*)d_in[2];
    const float* cl1_g  = (const float*)d_in[3];
    const float* cl1_bt = (const float*)d_in[4];
    const float* cl1_m  = (const float*)d_in[5];
    const float* cl1_v  = (const float*)d_in[6];
    const float* cl2_w  = (const float*)d_in[7];
    const float* cl2_b  = (const float*)d_in[8];
    const float* cl3_w  = (const float*)d_in[9];
    const float* cl3_b  = (const float*)d_in[10];
    const float* reg1_w = (const float*)d_in[11];
    const float* reg1_b = (const float*)d_in[12];
    const float* reg1_g = (const float*)d_in[13];
    const float* reg1_bt= (const float*)d_in[14];
    const float* reg1_m = (const float*)d_in[15];
    const float* reg1_v = (const float*)d_in[16];
    const float* w2     = (const float*)d_in[17];
    const float* b2     = (const float*)d_in[18];
    const float* w3     = (const float*)d_in[19];
    const float* b3     = (const float*)d_in[20];
    float* out = (float*)d_out;

    cudaFuncSetAttribute(main_kernel,
                         cudaFuncAttributeMaxDynamicSharedMemorySize,
                         (int)SMEM_BYTES);

    prep_kernel<<<64, 256>>>(cl1_w, cl1_b, cl1_g, cl1_bt, cl1_m, cl1_v,
                             reg1_w, reg1_b, reg1_g, reg1_bt, reg1_m, reg1_v);
    main_kernel<<<1024, 256, SMEM_BYTES>>>(x_in, cl2_w, cl2_b, cl3_w, cl3_b,
                                           w2, b2, w3, b3, out);
}